// round 16
// baseline (speedup 1.0000x reference)
#include <cuda_runtime.h>
#include <cuda_fp16.h>
#include <math.h>
#include <stdint.h>

// ---------------- problem constants ----------------
#define NF      32
#define C       64
#define H       96
#define W       96
#define FEAT    2304
#define DIM     768
#define M_TOK   (NF*256)                    // 8192
#define TOK_ELEMS   (M_TOK*DIM)
#define FRAME_STRIDE (C*H*W)

__device__ __forceinline__ float gelu_exact(float x){
    return 0.5f*x*(1.0f + erff(x*0.7071067811865476f));
}
__device__ __forceinline__ void mma_f16(float* d, const uint32_t* a, const uint32_t* b){
    asm volatile(
        "mma.sync.aligned.m16n8k16.row.col.f32.f16.f16.f32 "
        "{%0,%1,%2,%3}, {%4,%5,%6,%7}, {%8,%9}, {%0,%1,%2,%3};"
        : "+f"(d[0]), "+f"(d[1]), "+f"(d[2]), "+f"(d[3])
        : "r"(a[0]), "r"(a[1]), "r"(a[2]), "r"(a[3]), "r"(b[0]), "r"(b[1]));
}
__device__ __forceinline__ void cp16(uint32_t saddr, const void* g){
    asm volatile("cp.async.cg.shared.global [%0], [%1], 16;" :: "r"(saddr), "l"(g));
}
__device__ __forceinline__ uint32_t packh2(__half a, __half b){
    uint32_t lo = (uint32_t)__half_as_ushort(a);
    uint32_t hi = (uint32_t)__half_as_ushort(b);
    return (hi << 16) | lo;
}
__device__ __forceinline__ uint32_t smem_u32(const void* p){
    return (uint32_t)__cvta_generic_to_shared(p);
}

// ---------------- device globals ----------------
// conv weights u64 pairs: [tap][cg][lt(0..3)][co] = { fp16x2(ci=2lt,2lt+1), fp16x2(ci=2(lt+4),..+1) }
__device__ unsigned long long g_wf2[9*4*4*64];
__device__ float g_bnscale[64];
__device__ float g_bnshift[64];
__device__ __half g_w16[DIM*FEAT];         // proj_w fp16 (filled by conv kernel)
__device__ __half g_a16[(long)M_TOK*FEAT]; // masked patches fp16

// =====================================================================
// Kernel 0: conv-weight u64-pair repack + BN fold (tiny: 36 blocks)
// =====================================================================
__global__ void prep_kernel(const float* __restrict__ cw,
                            const float* __restrict__ cb,
                            const float* __restrict__ gamma,
                            const float* __restrict__ beta,
                            const float* __restrict__ mean,
                            const float* __restrict__ var)
{
    int idx = blockIdx.x*256 + threadIdx.x;
    if (idx < 9*4*4*64){
        int co  = idx & 63;
        int lt  = (idx >> 6) & 3;
        int cg  = (idx >> 8) & 3;
        int tap = idx >> 10;
        int cA = cg*16 + 2*lt;          // k = lt
        int cB = cg*16 + 2*(lt+4);      // k = lt+4
        uint32_t lo = packh2(__float2half_rn(cw[(co*64 + cA)*9 + tap]),
                             __float2half_rn(cw[(co*64 + cA + 1)*9 + tap]));
        uint32_t hi = packh2(__float2half_rn(cw[(co*64 + cB)*9 + tap]),
                             __float2half_rn(cw[(co*64 + cB + 1)*9 + tap]));
        g_wf2[idx] = ((unsigned long long)hi << 32) | lo;
    }
    if (blockIdx.x == 0 && threadIdx.x < 64){
        int co = threadIdx.x;
        float s = gamma[co] * rsqrtf(var[co] + 1e-5f);
        g_bnscale[co] = s;
        g_bnshift[co] = (cb[co] - mean[co]) * s + beta[co];
    }
}

// =====================================================================
// Kernel 1: conv3x3 implicit GEMM, fp16 mma, sw-pipelined, u64-paired
// operands: every fragment pair is ONE LDS.64 (8 LDS.64 : 8 mma per
// warp-tap). Conflict-free (c/lt strides ≡ 24 mod 32 banks).
// Also folds proj_w fp32->fp16 conversion (768 elems/block).
// =====================================================================
#define CV_SX2 992                  // u64/buffer: 8c × (10y*12xp, stride 124)
#define CV_SB2 (9*4*76)             // u64/buffer: 2736
#define CV_SMEM_BYTES ((2*CV_SX2 + 2*CV_SB2)*8)   // 59,648

__global__ __launch_bounds__(256, 2) void conv_mma_kernel(
    const float* __restrict__ x,
    const float* __restrict__ mask,
    float* __restrict__ out_patches,
    const float* __restrict__ pw)
{
    extern __shared__ __align__(16) unsigned long long dynsm64[];
    unsigned long long* s_x = dynsm64;                 // [buf][c*124 + y*12 + xp]
    unsigned long long* s_b = dynsm64 + 2*CV_SX2;      // [buf][(tap*4+lt)*76 + co]

    __shared__ float s_mask[36];
    __shared__ float s_scale[64], s_shift[64];

    const int tid  = threadIdx.x;
    const int lane = tid & 31;
    const int wid  = tid >> 5;
    const int wm   = wid & 3;
    const int wn   = wid >> 2;
    const int lg   = lane >> 2;      // 0..7
    const int lt   = lane & 3;       // 0..3

    const int w0    = blockIdx.x * 16;
    const int h0    = blockIdx.y * 8;
    const int frame = blockIdx.z;
    const float* xf = x + (long)frame * FRAME_STRIDE;

    if (tid < 36) s_mask[tid] = mask[tid];
    if (tid < 64){ s_scale[tid] = g_bnscale[tid]; s_shift[tid] = g_bnshift[tid]; }

    // halo pair-staging geometry: 960 slots = 8c x 10y x 12xp, 4 per thread
    int hp_idx[4];        // u64 index within buffer
    int hp_gy[4], hp_gx[4], hp_c[4];
    bool okA[4], okB[4];
    #pragma unroll
    for (int j = 0; j < 4; j++){
        int i = tid + j*256;
        bool valid = (i < 960);
        int c   = valid ? i / 120 : 0;
        int rem = valid ? i - c*120 : 0;
        int y   = rem / 12;
        int xp  = rem - y*12;
        hp_c[j]   = c;
        hp_gy[j]  = h0 + y - 1;
        hp_gx[j]  = w0 + xp - 1;
        hp_idx[j] = c*124 + y*12 + xp;
        bool gyok = valid && hp_gy[j] >= 0 && hp_gy[j] < H;
        okA[j] = gyok && hp_gx[j] >= 0 && hp_gx[j] < W;
        okB[j] = gyok && (hp_gx[j] + 8) < W;
        if (!valid) hp_idx[j] = -1;
    }

    auto ldhalo = [&](int cbase, float* vA0, float* vA1, float* vB0, float* vB1){
        #pragma unroll
        for (int j = 0; j < 4; j++){
            vA0[j]=0.f; vA1[j]=0.f; vB0[j]=0.f; vB1[j]=0.f;
            long basep = (long)(cbase + 2*hp_c[j])*(H*W) + (long)hp_gy[j]*W;
            if (okA[j]){
                vA0[j] = xf[basep + hp_gx[j]];
                vA1[j] = xf[basep + H*W + hp_gx[j]];
            }
            if (okB[j]){
                vB0[j] = xf[basep + hp_gx[j] + 8];
                vB1[j] = xf[basep + H*W + hp_gx[j] + 8];
            }
        }
    };
    auto sthalo = [&](unsigned long long* dst, const float* vA0, const float* vA1,
                      const float* vB0, const float* vB1){
        #pragma unroll
        for (int j = 0; j < 4; j++){
            if (hp_idx[j] >= 0){
                uint32_t lo = packh2(__float2half_rn(vA0[j]), __float2half_rn(vA1[j]));
                uint32_t hi = packh2(__float2half_rn(vB0[j]), __float2half_rn(vB1[j]));
                dst[hp_idx[j]] = ((unsigned long long)hi << 32) | lo;
            }
        }
    };
    auto issueB = [&](unsigned long long* dst, int cg){
        for (int i = tid; i < 1152; i += 256){
            int q   = i & 31;
            int row = i >> 5;            // 0..35 = tap*4 + lt
            int tap = row >> 2, l = row & 3;
            cp16(smem_u32(dst + row*76 + q*2),
                 g_wf2 + (((long)(tap*4 + cg)*4 + l)*64 + q*2));
        }
        asm volatile("cp.async.commit_group;" ::: "memory");
    };

    float acc[2][4][4];
    #pragma unroll
    for (int mt=0;mt<2;mt++)
        #pragma unroll
        for (int nt=0;nt<4;nt++)
            #pragma unroll
            for (int r=0;r<4;r++) acc[mt][nt][r] = 0.f;

    // ---- prologue: stage cg=0 into buffer 0 ----
    issueB(s_b, 0);
    {
        float a0[4], a1[4], b0[4], b1[4];
        ldhalo(0, a0, a1, b0, b1);
        sthalo(s_x, a0, a1, b0, b1);
    }
    asm volatile("cp.async.wait_group 0;" ::: "memory");
    __syncthreads();

    for (int cg = 0; cg < 4; cg++){
        const int cur = cg & 1;
        const int nxt = cur ^ 1;
        const bool hasnext = (cg < 3);
        const unsigned long long* px_ = s_x + cur*CV_SX2;
        const unsigned long long* pb_ = s_b + cur*CV_SB2;

        float nA0[4], nA1[4], nB0[4], nB1[4];
        if (hasnext){
            issueB(s_b + nxt*CV_SB2, cg + 1);
            ldhalo((cg + 1)*16, nA0, nA1, nB0, nB1);
        }

        // ---- 9 taps: 8 LDS.64 + 8 mma per warp-tap, no barriers ----
        #pragma unroll
        for (int tap = 0; tap < 9; tap++){
            const int ky = tap / 3, kx = tap - ky*3;
            uint32_t a[2][4], b[4][2];
            #pragma unroll
            for (int mt = 0; mt < 2; mt++){
                const int py = wm*2 + mt + ky;
                const int xp = lg + kx;
                uint2 v0 = *(const uint2*)&px_[lt*124     + py*12 + xp];
                uint2 v1 = *(const uint2*)&px_[(lt+4)*124 + py*12 + xp];
                a[mt][0] = v0.x;   // (k=lt,   px)
                a[mt][1] = v0.y;   // (k=lt,   px+8)
                a[mt][2] = v1.x;   // (k=lt+4, px)
                a[mt][3] = v1.y;   // (k=lt+4, px+8)
            }
            #pragma unroll
            for (int nt = 0; nt < 4; nt++){
                const int co = wn*32 + nt*8 + lg;
                uint2 bv = *(const uint2*)&pb_[(tap*4 + lt)*76 + co];
                b[nt][0] = bv.x;   // k = lt
                b[nt][1] = bv.y;   // k = lt+4
            }
            #pragma unroll
            for (int mt = 0; mt < 2; mt++)
                #pragma unroll
                for (int nt = 0; nt < 4; nt++)
                    mma_f16(acc[mt][nt], a[mt], b[nt]);
        }

        if (hasnext){
            sthalo(s_x + nxt*CV_SX2, nA0, nA1, nB0, nB1);
            asm volatile("cp.async.wait_group 0;" ::: "memory");
            __syncthreads();
        }
    }

    // ---- epilogue: BN + GELU + mask -> patches (fp32) + fp16 A copy ----
    #pragma unroll
    for (int mt = 0; mt < 2; mt++){
        const int r0 = wm*32 + mt*16 + lg;
        #pragma unroll
        for (int dr = 0; dr < 2; dr++){
            const int r = r0 + dr*8;
            const int hh = h0 + (r >> 4);
            const int ww = w0 + (r & 15);
            const int l = hh / 6, i_in = hh - l*6;
            const int rr = ww / 6, j_in = ww - rr*6;
            const float mk = s_mask[i_in*6 + j_in];
            const long arow = ((long)frame*256 + l*16 + rr)*FEAT;
            #pragma unroll
            for (int nt = 0; nt < 4; nt++){
                const int c0 = wn*32 + nt*8 + (lt << 1);
                #pragma unroll
                for (int dc = 0; dc < 2; dc++){
                    const int co = c0 + dc;
                    const float v = acc[mt][nt][dr*2 + dc];
                    float o = gelu_exact(v*s_scale[co] + s_shift[co]) * mk;
                    const long k = arow + co*36 + i_in*6 + j_in;
                    out_patches[k] = o;
                    g_a16[k] = __float2half_rn(o);
                }
            }
        }
    }

    // ---- folded proj_w conversion: 768 elements per block ----
    {
        const long pbase = ((long)blockIdx.z*72 + blockIdx.y*6 + blockIdx.x) * 768;
        for (int e = tid; e < 768; e += 256)
            g_w16[pbase + e] = __float2half_rn(pw[pbase + e]);
    }
}

// =====================================================================
// Kernel 2: tokens GEMM, fp16 m16n8k16, 32x48 warp tile
// (round-15 kernel, known good, unchanged)
// =====================================================================
#define GBM 128
#define GBN 96
#define GBK 64
#define KSTR 36
#define STAGES 3
#define SA_WORDS (GBM*KSTR)
#define SB_WORDS (GBN*KSTR)
#define GEMM_SMEM_BYTES ((STAGES*(SA_WORDS+SB_WORDS))*4)   // 96768

__global__ __launch_bounds__(256, 2) void gemm_tokens_f16_kernel(
    const float* __restrict__ bias,
    float* __restrict__ tok)
{
    extern __shared__ uint32_t smdyn[];
    uint32_t* s_a = smdyn;
    uint32_t* s_b = smdyn + STAGES*SA_WORDS;
    const uint32_t sa_base = smem_u32(s_a);
    const uint32_t sb_base = smem_u32(s_b);

    const int tid  = threadIdx.x;
    const int lane = tid & 31;
    const int wid  = tid >> 5;
    const int wm   = wid & 3;
    const int wn   = wid >> 2;
    const int bm   = blockIdx.y;
    const int bn   = blockIdx.x;

    const __half* Ab = g_a16 + (long)bm*GBM*FEAT;
    const __half* Bb = g_w16 + (long)bn*GBN*FEAT;

    float acc[2][6][4];
    #pragma unroll
    for (int mt=0;mt<2;mt++)
        #pragma unroll
        for (int nt=0;nt<6;nt++)
            #pragma unroll
            for (int r=0;r<4;r++) acc[mt][nt][r] = 0.f;

    const int crowA = tid >> 3;
    const int ck4   = (tid & 7) << 2;
    const int ckh   = ck4 << 1;

    #pragma unroll
    for (int st = 0; st < 2; st++){
        const int kg = st*GBK;
        #pragma unroll
        for (int j = 0; j < 4; j++){
            int row = crowA + j*32;
            cp16(sa_base + (uint32_t)((st*GBM + row)*KSTR + ck4)*4,
                 Ab + (long)row*FEAT + kg + ckh);
        }
        #pragma unroll
        for (int j = 0; j < 3; j++){
            int row = crowA + j*32;
            cp16(sb_base + (uint32_t)((st*GBN + row)*KSTR + ck4)*4,
                 Bb + (long)row*FEAT + kg + ckh);
        }
        asm volatile("cp.async.commit_group;");
    }
    asm volatile("cp.async.wait_group 1;");
    __syncthreads();

    const int NKT = FEAT / GBK;   // 36
    for (int kt = 0; kt < NKT; kt++){
        const int cur = kt % STAGES;
        if (kt + 2 < NKT){
            const int st = (kt + 2) % STAGES;
            const int kg = (kt + 2)*GBK;
            #pragma unroll
            for (int j = 0; j < 4; j++){
                int row = crowA + j*32;
                cp16(sa_base + (uint32_t)((st*GBM + row)*KSTR + ck4)*4,
                     Ab + (long)row*FEAT + kg + ckh);
            }
            #pragma unroll
            for (int j = 0; j < 3; j++){
                int row = crowA + j*32;
                cp16(sb_base + (uint32_t)((st*GBN + row)*KSTR + ck4)*4,
                     Bb + (long)row*FEAT + kg + ckh);
            }
        }
        asm volatile("cp.async.commit_group;");

        const uint32_t* pa = s_a + cur*SA_WORDS;
        const uint32_t* pb = s_b + cur*SB_WORDS;
        #pragma unroll
        for (int ks = 0; ks < 4; ks++){
            const int kb = ks*8 + (lane & 3);
            uint32_t af[2][4], bf[6][2];
            #pragma unroll
            for (int mt=0;mt<2;mt++){
                int r0 = wm*32 + mt*16 + (lane >> 2);
                af[mt][0] = pa[r0*KSTR + kb];
                af[mt][1] = pa[(r0+8)*KSTR + kb];
                af[mt][2] = pa[r0*KSTR + kb + 4];
                af[mt][3] = pa[(r0+8)*KSTR + kb + 4];
            }
            #pragma unroll
            for (int nt=0;nt<6;nt++){
                int c0 = wn*48 + nt*8 + (lane >> 2);
                bf[nt][0] = pb[c0*KSTR + kb];
                bf[nt][1] = pb[c0*KSTR + kb + 4];
            }
            #pragma unroll
            for (int mt=0;mt<2;mt++)
                #pragma unroll
                for (int nt=0;nt<6;nt++)
                    mma_f16(acc[mt][nt], af[mt], bf[nt]);
        }

        asm volatile("cp.async.wait_group 1;");
        __syncthreads();
    }

    #pragma unroll
    for (int mt=0;mt<2;mt++){
        const int r0 = bm*GBM + wm*32 + mt*16 + (lane >> 2);
        #pragma unroll
        for (int nt=0;nt<6;nt++){
            const int c0 = bn*GBN + wn*48 + nt*8 + ((lane & 3) << 1);
            float2 b2 = *(const float2*)(bias + c0);
            float2 o0, o1;
            o0.x = gelu_exact(acc[mt][nt][0] + b2.x);
            o0.y = gelu_exact(acc[mt][nt][1] + b2.y);
            o1.x = gelu_exact(acc[mt][nt][2] + b2.x);
            o1.y = gelu_exact(acc[mt][nt][3] + b2.y);
            *(float2*)(tok + (long)r0*DIM + c0)     = o0;
            *(float2*)(tok + (long)(r0+8)*DIM + c0) = o1;
        }
    }
}

// =====================================================================
extern "C" void kernel_launch(void* const* d_in, const int* in_sizes, int n_in,
                              void* d_out, int out_size)
{
    const float* x      = (const float*)d_in[0];
    const float* conv_w = (const float*)d_in[1];
    const float* conv_b = (const float*)d_in[2];
    const float* gamma  = (const float*)d_in[3];
    const float* beta   = (const float*)d_in[4];
    const float* mean   = (const float*)d_in[5];
    const float* var    = (const float*)d_in[6];
    const float* proj_w = (const float*)d_in[7];
    const float* proj_b = (const float*)d_in[8];
    const float* mask   = (const float*)d_in[9];

    float* tokens  = (float*)d_out;                 // [8192, 768]
    float* patches = (float*)d_out + TOK_ELEMS;     // [8192, 2304]

    cudaFuncSetAttribute(conv_mma_kernel,
                         cudaFuncAttributeMaxDynamicSharedMemorySize,
                         CV_SMEM_BYTES);
    cudaFuncSetAttribute(gemm_tokens_f16_kernel,
                         cudaFuncAttributeMaxDynamicSharedMemorySize,
                         GEMM_SMEM_BYTES);

    // 0) tiny prep: conv-weight u64 pairs + BN fold
    prep_kernel<<<36, 256>>>(conv_w, conv_b, gamma, beta, mean, var);

    // 1) conv implicit GEMM (paired LDS.64 operands) + proj_w cvt fold
    {
        dim3 grid(W/16, H/8, NF);
        conv_mma_kernel<<<grid, 256, CV_SMEM_BYTES>>>(x, mask, patches, proj_w);
    }

    // 2) projection GEMM + bias + GELU (fp16 m16n8k16, 32x48 warp tile)
    {
        dim3 grid(DIM/GBN, M_TOK/GBM);   // (8, 64)
        gemm_tokens_f16_kernel<<<grid, 256, GEMM_SMEM_BYTES>>>(proj_b, tokens);
    }
}